// round 1
// baseline (speedup 1.0000x reference)
#include <cuda_runtime.h>

// Izhikevich RS constants (match reference)
#define P_A 0.02f
#define P_B 0.2f
#define P_C (-65.0f)
#define P_D 8.0f
#define I_TONIC (-3.0f)
// W_rec: diag = 4.0, offdiag = -2.0  =>  I_rec[i] = 6*r[i] - 2*sum(r)

__global__ void spiking_goal_selector_kernel(
    const float* __restrict__ pal_d_rate,   // (3072,)
    const float* __restrict__ neuromod_bias,// (4,)
    const float* __restrict__ W,            // (4, 3072) row-major
    const int*   __restrict__ substeps_p,   // scalar
    float* __restrict__ out, int out_size, int n_e)
{
    __shared__ float I_sh[4];

    const int warp = threadIdx.x >> 5;
    const int lane = threadIdx.x & 31;

    // ---- matvec: warp w computes row w of W @ pal_d_rate, float4 vectorized ----
    // n_e = 3072 -> 768 float4 per row, 24 per lane.
    float s = 0.0f;
    if (warp < 4) {
        const float4* Wr = reinterpret_cast<const float4*>(W + (size_t)warp * n_e);
        const float4* xr = reinterpret_cast<const float4*>(pal_d_rate);
        const int nv4 = n_e >> 2;
        for (int i = lane; i < nv4; i += 32) {
            float4 w = Wr[i];
            float4 x = xr[i];
            s += w.x * x.x + w.y * x.y + w.z * x.z + w.w * x.w;
        }
        #pragma unroll
        for (int o = 16; o > 0; o >>= 1)
            s += __shfl_down_sync(0xffffffffu, s, o);
        if (lane == 0) I_sh[warp] = s;
    }
    __syncthreads();

    // ---- serial WTA dynamics on thread 0 (4 neurons, `substeps` steps) ----
    if (threadIdx.x == 0) {
        const int T = *substeps_p;

        float Ip[4];
        float m = 0.0f;
        #pragma unroll
        for (int i = 0; i < 4; i++) { Ip[i] = I_sh[i]; m += fabsf(Ip[i]); }
        m = m * 0.25f + 1e-8f;
        const float scale = (m > 1e-3f) ? (3.0f / m) : 0.0f;
        #pragma unroll
        for (int i = 0; i < 4; i++)
            Ip[i] = Ip[i] * scale + neuromod_bias[i] * 2.0f + I_TONIC;

        float v[4], u[4], r[4], cnt[4];
        #pragma unroll
        for (int i = 0; i < 4; i++) {
            v[i] = P_C; u[i] = P_B * P_C; r[i] = 0.0f; cnt[i] = 0.0f;
        }

        for (int t = 0; t < T; t++) {
            const float rsum = r[0] + r[1] + r[2] + r[3];
            #pragma unroll
            for (int i = 0; i < 4; i++) {
                const float I_rec = 6.0f * r[i] - 2.0f * rsum;
                const float I = Ip[i] + I_rec;
                float vn = v[i] + (0.04f * v[i] * v[i] + 5.0f * v[i] + 140.0f - u[i] + I);
                float un = u[i] + P_A * (P_B * v[i] - u[i]);
                const float sp = (vn >= 30.0f) ? 1.0f : 0.0f;
                if (sp > 0.0f) { vn = P_C; un += P_D; }
                r[i]   = 0.9f * r[i] + 0.1f * sp;
                cnt[i] += sp;
                v[i] = vn; u[i] = un;
            }
        }

        const float invT = 1.0f / (float)T;
        float rates[4], rsum2 = 0.0f;
        int win = 0; float best = rates[0] = cnt[0] * invT;
        rsum2 = rates[0];
        #pragma unroll
        for (int i = 1; i < 4; i++) {
            rates[i] = cnt[i] * invT;
            rsum2 += rates[i];
            if (rates[i] > best) { best = rates[i]; win = i; }
        }

        // Output layout: [rates(4), winner, confidence]
        #pragma unroll
        for (int i = 0; i < 4 && i < out_size; i++) out[i] = rates[i];
        if (out_size > 4) out[4] = (float)win;
        if (out_size > 5) out[5] = best / (rsum2 + 1e-8f);
    }
}

extern "C" void kernel_launch(void* const* d_in, const int* in_sizes, int n_in,
                              void* d_out, int out_size)
{
    const float* pal_d_rate    = (const float*)d_in[0];   // 3072
    const float* neuromod_bias = (const float*)d_in[1];   // 4
    const float* W_pald_goal   = (const float*)d_in[2];   // 4*3072
    const int*   substeps      = (const int*)  d_in[3];   // 1
    float* out = (float*)d_out;
    const int n_e = in_sizes[0];

    spiking_goal_selector_kernel<<<1, 128>>>(
        pal_d_rate, neuromod_bias, W_pald_goal, substeps, out, out_size, n_e);
}

// round 2
// speedup vs baseline: 1.4513x; 1.4513x over previous
#include <cuda_runtime.h>

// Izhikevich RS constants (match reference)
#define P_A 0.02f
#define P_B 0.2f
#define P_C (-65.0f)
#define P_D 8.0f
#define I_TONIC (-3.0f)
// W_rec: diag = 4.0, offdiag = -2.0  =>  I_rec[i] = 6*r[i] - 2*sum(r)

__global__ void __launch_bounds__(512, 1)
spiking_goal_selector_kernel(
    const float* __restrict__ pal_d_rate,   // (3072,)
    const float* __restrict__ neuromod_bias,// (4,)
    const float* __restrict__ W,            // (4, 3072) row-major
    const int*   __restrict__ substeps_p,   // scalar
    float* __restrict__ out, int out_size, int n_e)
{
    __shared__ float part[16];   // one partial per warp

    const int warp = threadIdx.x >> 5;
    const int lane = threadIdx.x & 31;

    // ---- hoist scalar loads: issue at kernel entry, consumed after barrier ----
    int   T  = 0;
    float b0 = 0.f, b1 = 0.f, b2 = 0.f, b3 = 0.f;
    if (threadIdx.x == 0) {
        T  = *substeps_p;
        b0 = neuromod_bias[0];
        b1 = neuromod_bias[1];
        b2 = neuromod_bias[2];
        b3 = neuromod_bias[3];
    }

    // ---- matvec: 16 warps, 4 per row; each lane does exactly q/32 float4s ----
    // n_e = 3072 -> nv4 = 768, q = 192 per warp-slice, 6 float4 per lane,
    // fully unrolled -> 12 independent LDG.128 in flight per lane.
    const int row = warp >> 2;
    const int p   = warp & 3;
    const int nv4 = n_e >> 2;
    const int q   = nv4 >> 2;          // float4s per warp-slice
    const float4* Wr = reinterpret_cast<const float4*>(W + (size_t)row * n_e) + p * q;
    const float4* xr = reinterpret_cast<const float4*>(pal_d_rate) + p * q;

    float s = 0.0f;
    #pragma unroll 6
    for (int i = lane; i < q; i += 32) {
        float4 w = Wr[i];
        float4 x = xr[i];
        s += w.x * x.x + w.y * x.y + w.z * x.z + w.w * x.w;
    }
    #pragma unroll
    for (int o = 16; o > 0; o >>= 1)
        s += __shfl_down_sync(0xffffffffu, s, o);
    if (lane == 0) part[warp] = s;
    __syncthreads();

    // ---- serial WTA dynamics on thread 0 (4 neurons, T steps) ----
    if (threadIdx.x == 0) {
        float Ip[4];
        float m = 0.0f;
        #pragma unroll
        for (int i = 0; i < 4; i++) {
            Ip[i] = part[4*i] + part[4*i+1] + part[4*i+2] + part[4*i+3];
            m += fabsf(Ip[i]);
        }
        m = m * 0.25f + 1e-8f;
        const float scale = (m > 1e-3f) ? (3.0f / m) : 0.0f;
        const float bias[4] = {b0, b1, b2, b3};
        #pragma unroll
        for (int i = 0; i < 4; i++)
            Ip[i] = Ip[i] * scale + bias[i] * 2.0f + I_TONIC;

        float v[4], u[4], r[4], cnt[4];
        #pragma unroll
        for (int i = 0; i < 4; i++) {
            v[i] = P_C; u[i] = P_B * P_C; r[i] = 0.0f; cnt[i] = 0.0f;
        }

        for (int t = 0; t < T; t++) {
            const float rsum = r[0] + r[1] + r[2] + r[3];
            #pragma unroll
            for (int i = 0; i < 4; i++) {
                const float I_rec = 6.0f * r[i] - 2.0f * rsum;
                const float I = Ip[i] + I_rec;
                float vn = v[i] + (0.04f * v[i] * v[i] + 5.0f * v[i] + 140.0f - u[i] + I);
                float un = u[i] + P_A * (P_B * v[i] - u[i]);
                const float sp = (vn >= 30.0f) ? 1.0f : 0.0f;
                if (sp > 0.0f) { vn = P_C; un += P_D; }
                r[i]   = 0.9f * r[i] + 0.1f * sp;
                cnt[i] += sp;
                v[i] = vn; u[i] = un;
            }
        }

        const float invT = 1.0f / (float)T;
        float rates[4];
        float rsum2 = 0.0f;
        int win = 0; float best = -1.0f;
        #pragma unroll
        for (int i = 0; i < 4; i++) {
            rates[i] = cnt[i] * invT;
            rsum2 += rates[i];
            if (rates[i] > best) { best = rates[i]; win = i; }
        }

        // Output layout: [rates(4), winner, confidence]
        #pragma unroll
        for (int i = 0; i < 4; i++) if (i < out_size) out[i] = rates[i];
        if (out_size > 4) out[4] = (float)win;
        if (out_size > 5) out[5] = best / (rsum2 + 1e-8f);
    }
}

extern "C" void kernel_launch(void* const* d_in, const int* in_sizes, int n_in,
                              void* d_out, int out_size)
{
    const float* pal_d_rate    = (const float*)d_in[0];   // 3072
    const float* neuromod_bias = (const float*)d_in[1];   // 4
    const float* W_pald_goal   = (const float*)d_in[2];   // 4*3072
    const int*   substeps      = (const int*)  d_in[3];   // 1
    float* out = (float*)d_out;
    const int n_e = in_sizes[0];

    spiking_goal_selector_kernel<<<1, 512>>>(
        pal_d_rate, neuromod_bias, W_pald_goal, substeps, out, out_size, n_e);
}